// round 2
// baseline (speedup 1.0000x reference)
#include <cuda_runtime.h>
#include <cstdint>

#define A_TOT 49056
#define BATCH 32
#define NFG 7
#define KTOP 200
#define MIMG (NFG*KTOP)        // 1400
#define NMS_THR_F 0.45f
#define LOW_SCORE_F 0.01f

// ---------------- scratch (device globals; no runtime allocation) ------------
__device__ float  g_fg[(size_t)BATCH * NFG * A_TOT];   // [b][c][a] fg softmax scores
__device__ float4 g_boxes[(size_t)BATCH * A_TOT];      // [b][a] clipped decoded boxes
__device__ float  g_cs[BATCH * NFG * KTOP];            // per-class top-200 scores
__device__ int    g_ca[BATCH * NFG * KTOP];            // per-class top-200 anchor idx
__device__ float  g_s2[BATCH * MIMG];                  // post-NMS scores (-inf if dropped)
__device__ int    g_m2[BATCH * MIMG];                  // packed meta: anchor | label<<16

__device__ __forceinline__ unsigned fkey(float f) {
    unsigned u = __float_as_uint(f);
    return (u & 0x80000000u) ? ~u : (u | 0x80000000u);
}
__device__ __forceinline__ float funkey(unsigned k) {
    unsigned u = (k & 0x80000000u) ? (k & 0x7fffffffu) : ~k;
    return __uint_as_float(u);
}

// ---------------- K1: softmax + decode ---------------------------------------
__global__ void k_prep(const float* __restrict__ logits,
                       const float* __restrict__ deltas,
                       const float* __restrict__ dbox) {
    int idx = blockIdx.x * blockDim.x + threadIdx.x;
    if (idx >= BATCH * A_TOT) return;
    int b = idx / A_TOT;
    int a = idx - b * A_TOT;

    float4 l0 = ((const float4*)logits)[idx * 2 + 0];
    float4 l1 = ((const float4*)logits)[idx * 2 + 1];
    float x[8] = {l0.x, l0.y, l0.z, l0.w, l1.x, l1.y, l1.z, l1.w};
    float mx = x[0];
#pragma unroll
    for (int i = 1; i < 8; i++) mx = fmaxf(mx, x[i]);
    float e[8]; float sum = 0.f;
#pragma unroll
    for (int i = 0; i < 8; i++) { e[i] = expf(x[i] - mx); sum += e[i]; }
    float inv = 1.0f / sum;
#pragma unroll
    for (int c = 0; c < NFG; c++)
        g_fg[((size_t)b * NFG + c) * A_TOT + a] = e[c + 1] * inv;

    float4 d  = ((const float4*)deltas)[idx];
    float4 db = ((const float4*)dbox)[a];
    float w  = db.z - db.x,  h  = db.w - db.y;
    float cx = db.x + 0.5f * w, cy = db.y + 0.5f * h;
    float pcx = d.x / 10.0f * w + cx;
    float pcy = d.y / 10.0f * h + cy;
    float pw  = expf(d.z / 5.0f) * w;
    float ph  = expf(d.w / 5.0f) * h;
    float bx0 = fminf(fmaxf(pcx - 0.5f * pw, 0.f), 1.f);
    float by0 = fminf(fmaxf(pcy - 0.5f * ph, 0.f), 1.f);
    float bx1 = fminf(fmaxf(pcx + 0.5f * pw, 0.f), 1.f);
    float by1 = fminf(fmaxf(pcy + 0.5f * ph, 0.f), 1.f);
    g_boxes[idx] = make_float4(bx0, by0, bx1, by1);
}

// ---------------- K2: exact per-class top-200 radix select -------------------
__global__ void k_topk() {
    int bc = blockIdx.x;                       // b*7 + c
    const float* sc = g_fg + (size_t)bc * A_TOT;
    __shared__ int hist[256];
    __shared__ unsigned sh_prefix;
    __shared__ int sh_krem;
    __shared__ int cnt_gt, eq_cnt;
    __shared__ int eq_idx[256];
    int tid = threadIdx.x;                     // 256 threads

    unsigned prefix = 0;
    int krem = KTOP;
    for (int round = 0; round < 4; round++) {
        hist[tid] = 0;
        __syncthreads();
        int shift = 24 - 8 * round;
        for (int base = 0; base < A_TOT; base += 256) {
            int i = base + tid;
            bool act = false; unsigned bin = 0;
            if (i < A_TOT) {
                unsigned key = __float_as_uint(sc[i]);
                act = (round == 0) || ((key >> (shift + 8)) == prefix);
                bin = (key >> shift) & 255u;
            }
            // warp-aggregated histogram (scores are concentrated -> same bins)
            unsigned tag = act ? bin : (256u + (tid & 31));
            unsigned grp = __match_any_sync(0xffffffffu, tag);
            if (act && ((tid & 31) == (__ffs(grp) - 1)))
                atomicAdd(&hist[bin], __popc(grp));
        }
        __syncthreads();
        if (tid == 0) {
            int cum = 0;
            for (int t = 255; t >= 0; t--) {
                cum += hist[t];
                if (cum >= krem) {
                    sh_prefix = (prefix << 8) | (unsigned)t;
                    sh_krem = krem - (cum - hist[t]);
                    break;
                }
            }
        }
        __syncthreads();
        prefix = sh_prefix; krem = sh_krem;
        __syncthreads();
    }
    unsigned V = prefix;   // exact 200th-largest key; krem = #equals to take

    if (tid == 0) { cnt_gt = 0; eq_cnt = 0; }
    __syncthreads();
    float* outs = g_cs + bc * KTOP;
    int*   outa = g_ca + bc * KTOP;
    for (int i = tid; i < A_TOT; i += 256) {
        unsigned key = __float_as_uint(sc[i]);
        if (key > V) {
            int p = atomicAdd(&cnt_gt, 1);
            outs[p] = __uint_as_float(key);
            outa[p] = i;
        } else if (key == V) {
            int p = atomicAdd(&eq_cnt, 1);
            if (p < 256) eq_idx[p] = i;
        }
    }
    __syncthreads();
    if (tid == 0) {
        int base = KTOP - krem;   // == cnt_gt by construction
        if (eq_cnt <= 256) {
            for (int t = 0; t < krem; t++) {        // smallest indices first (jax tie rule)
                int best = t;
                for (int u = t + 1; u < eq_cnt; u++)
                    if (eq_idx[u] < eq_idx[best]) best = u;
                int tmp = eq_idx[best]; eq_idx[best] = eq_idx[t]; eq_idx[t] = tmp;
                outs[base + t] = __uint_as_float(V);
                outa[base + t] = eq_idx[t];
            }
        } else {                                    // pathological fallback
            int taken = 0;
            for (int i = 0; i < A_TOT && taken < krem; i++)
                if (__float_as_uint(sc[i]) == V) {
                    outs[base + taken] = __uint_as_float(V);
                    outa[base + taken] = i; taken++;
                }
        }
    }
}

// ---------------- K3: per-(image,class) 200-candidate NMS --------------------
__global__ void k_nms() {
    int bc = blockIdx.x;
    int b = bc / NFG, c = bc % NFG;
    int tid = threadIdx.x;                     // 256 threads

    __shared__ unsigned skey[256];
    __shared__ int spay[256];
    if (tid < KTOP) { skey[tid] = fkey(g_cs[bc * KTOP + tid]); spay[tid] = tid; }
    else            { skey[tid] = 0; spay[tid] = tid; }
    __syncthreads();
    // bitonic sort 256, descending by key
    for (unsigned k = 2; k <= 256; k <<= 1)
        for (unsigned j = k >> 1; j > 0; j >>= 1) {
            unsigned t = tid, l = t ^ j;
            if (l > t) {
                bool desc = ((t & k) == 0);
                unsigned kt = skey[t], kl = skey[l];
                bool sw = desc ? (kt < kl) : (kt > kl);
                if (sw) { skey[t] = kl; skey[l] = kt; int p = spay[t]; spay[t] = spay[l]; spay[l] = p; }
            }
            __syncthreads();
        }

    __shared__ float x0[KTOP], y0[KTOP], x1[KTOP], y1[KTOP], ar[KTOP], ssc[KTOP];
    __shared__ int   san[KTOP];
    __shared__ unsigned mask[KTOP * 7];
    __shared__ unsigned remw[7];
    if (tid < KTOP) {
        int slot = spay[tid];
        float s  = g_cs[bc * KTOP + slot];
        int a    = g_ca[bc * KTOP + slot];
        float4 bx = g_boxes[(size_t)b * A_TOT + a];
        x0[tid] = bx.x; y0[tid] = bx.y; x1[tid] = bx.z; y1[tid] = bx.w;
        ar[tid] = (bx.z - bx.x) * (bx.w - bx.y);
        ssc[tid] = s; san[tid] = a;
    }
    for (int i = tid; i < KTOP * 7; i += 256) mask[i] = 0;
    __syncthreads();

    // suppression bitmask: bit (i,j) set if iou > thr (class offset unnecessary:
    // classes are fully separated by the +4*label trick in the reference)
    for (int p = tid; p < KTOP * KTOP; p += 256) {
        int i = p / KTOP, j = p - i * KTOP;
        if (j > i) {
            float xl = fmaxf(x0[i], x0[j]);
            float yt = fmaxf(y0[i], y0[j]);
            float xr = fminf(x1[i], x1[j]);
            float yb = fminf(y1[i], y1[j]);
            float iw = fmaxf(xr - xl, 0.f), ih = fmaxf(yb - yt, 0.f);
            float inter = iw * ih;
            float iou = inter / (ar[i] + ar[j] - inter);   // NaN -> comparison false (matches jax)
            if (iou > NMS_THR_F) atomicOr(&mask[i * 7 + (j >> 5)], 1u << (j & 31));
        }
    }
    __syncthreads();

    // greedy serial scan by warp 0 (lanes 0..6 own the 7 removed-words)
    if (tid < 32) {
        unsigned rem = 0;
        if (tid < 7) {
            for (int j = 0; j < 32; j++) {
                int jj = tid * 32 + j;
                if (jj < KTOP && !(ssc[jj] > LOW_SCORE_F)) rem |= 1u << j;  // low-score: never kept, never suppresses
            }
        }
        for (int i = 0; i < KTOP; i++) {
            unsigned rw = __shfl_sync(0xffffffffu, rem, i >> 5);
            if (!((rw >> (i & 31)) & 1u)) {
                if (tid < 7) rem |= mask[i * 7 + tid];
            }
        }
        if (tid < 7) remw[tid] = rem;
    }
    __syncthreads();

    if (tid < KTOP) {
        bool keep = !((remw[tid >> 5] >> (tid & 31)) & 1u);
        g_s2[bc * KTOP + tid] = keep ? ssc[tid] : __int_as_float(0xff800000); // -inf
        g_m2[bc * KTOP + tid] = san[tid] | ((c + 1) << 16);
    }
}

// ---------------- K4: per-image merge sort + emit top-200 --------------------
__global__ void k_out(float* __restrict__ out) {
    int b = blockIdx.x;
    int tid = threadIdx.x;                     // 1024 threads
    const int N = 2048;
    __shared__ unsigned key[2048];
    __shared__ int pay[2048];
    for (int t = tid; t < N; t += 1024) {
        if (t < MIMG) { key[t] = fkey(g_s2[b * MIMG + t]); pay[t] = g_m2[b * MIMG + t]; }
        else          { key[t] = 0; pay[t] = 0; }
    }
    __syncthreads();
    for (unsigned k = 2; k <= (unsigned)N; k <<= 1)
        for (unsigned j = k >> 1; j > 0; j >>= 1) {
            for (int t = tid; t < N; t += 1024) {
                unsigned l = (unsigned)t ^ j;
                if (l > (unsigned)t) {
                    bool desc = (((unsigned)t & k) == 0);
                    unsigned kt = key[t], kl = key[l];
                    bool sw = desc ? (kt < kl) : (kt > kl);
                    if (sw) { key[t] = kl; key[l] = kt; int p = pay[t]; pay[t] = pay[l]; pay[l] = p; }
                }
            }
            __syncthreads();
        }
    if (tid < KTOP) {
        float s = funkey(key[tid]);
        float4 bx = make_float4(0.f, 0.f, 0.f, 0.f);
        float so = 0.f, lo = 0.f;
        if (s > LOW_SCORE_F) {                 // kept scores are all > LOW_SCORE
            int m = pay[tid];
            int a = m & 0xffff;
            int lab = m >> 16;
            bx = g_boxes[(size_t)b * A_TOT + a];
            so = s; lo = (float)lab;
        }
        ((float4*)out)[b * KTOP + tid] = bx;                     // boxes  [B,200,4]
        out[BATCH * KTOP * 4 + b * KTOP + tid] = so;             // scores [B,200]
        out[BATCH * KTOP * 5 + b * KTOP + tid] = lo;             // labels [B,200]
    }
}

// -----------------------------------------------------------------------------
extern "C" void kernel_launch(void* const* d_in, const int* in_sizes, int n_in,
                              void* d_out, int out_size) {
    const float* logits = nullptr;
    const float* deltas = nullptr;
    const float* dbox   = nullptr;
    for (int i = 0; i < n_in; i++) {           // identify inputs by element count
        if      (in_sizes[i] == BATCH * A_TOT * 8) logits = (const float*)d_in[i];
        else if (in_sizes[i] == BATCH * A_TOT * 4) deltas = (const float*)d_in[i];
        else if (in_sizes[i] == A_TOT * 4)         dbox   = (const float*)d_in[i];
    }
    float* out = (float*)d_out;

    k_prep<<<(BATCH * A_TOT + 255) / 256, 256>>>(logits, deltas, dbox);
    k_topk<<<BATCH * NFG, 256>>>();
    k_nms<<<BATCH * NFG, 256>>>();
    k_out<<<BATCH, 1024>>>(out);
}

// round 3
// speedup vs baseline: 2.6764x; 2.6764x over previous
#include <cuda_runtime.h>
#include <cstdint>

#define A_TOT 49056
#define BATCH 32
#define NFG 7
#define KTOP 200
#define NBC (BATCH*NFG)          // 224
#define NBIN 4096
#define CANDMAX 2048
#define NMS_THR_F 0.45f
#define LOW_SCORE_F 0.01f

// ---------------- scratch (device globals; no runtime allocation) ------------
__device__ float4 g_boxes[(size_t)BATCH * A_TOT];        // decoded+clipped boxes
__device__ unsigned g_hist[NBC * NBIN];                  // per-(b,c) key histograms
__device__ int g_thrbin[NBC];                            // threshold bin per (b,c)
__device__ unsigned long long g_cand[(size_t)NBC * CANDMAX]; // (key<<32)|(A_TOT-a)
__device__ int g_ccnt[NBC];                              // candidate counts
__device__ float g_ks[NBC * KTOP];                       // kept scores (sorted)
__device__ int   g_km[NBC * KTOP];                       // kept anchors
__device__ int   g_kcnt[NBC];                            // kept counts

// identical softmax for k_prep and k_sel (bit-exact match required)
__device__ __forceinline__ void softmax8(const float4 l0, const float4 l1, float* fg7) {
    float x[8] = {l0.x, l0.y, l0.z, l0.w, l1.x, l1.y, l1.z, l1.w};
    float mx = x[0];
#pragma unroll
    for (int i = 1; i < 8; i++) mx = fmaxf(mx, x[i]);
    float e[8]; float sum = 0.f;
#pragma unroll
    for (int i = 0; i < 8; i++) { e[i] = expf(x[i] - mx); sum += e[i]; }
    float inv = 1.0f / sum;
#pragma unroll
    for (int c = 0; c < NFG; c++) fg7[c] = e[c + 1] * inv;
}

// ---------------- K0: zero scratch -------------------------------------------
__global__ void k_zero() {
    int i = blockIdx.x * 256 + threadIdx.x;
    if (i < NBC * NBIN) g_hist[i] = 0u;
    if (i < NBC) g_ccnt[i] = 0;
}

// ---------------- K1: softmax + decode + histogram ---------------------------
__global__ void k_prep(const float* __restrict__ logits,
                       const float* __restrict__ deltas,
                       const float* __restrict__ dbox) {
    int idx = blockIdx.x * blockDim.x + threadIdx.x;
    bool in = idx < BATCH * A_TOT;
    int b = 0, a = 0;
    float fg[NFG];
    if (in) {
        b = idx / A_TOT; a = idx - b * A_TOT;
        float4 l0 = ((const float4*)logits)[idx * 2 + 0];
        float4 l1 = ((const float4*)logits)[idx * 2 + 1];
        softmax8(l0, l1, fg);

        float4 d  = ((const float4*)deltas)[idx];
        float4 db = ((const float4*)dbox)[a];
        float w  = db.z - db.x,  h  = db.w - db.y;
        float cx = db.x + 0.5f * w, cy = db.y + 0.5f * h;
        float pcx = d.x / 10.0f * w + cx;
        float pcy = d.y / 10.0f * h + cy;
        float pw  = expf(d.z / 5.0f) * w;
        float ph  = expf(d.w / 5.0f) * h;
        g_boxes[idx] = make_float4(
            fminf(fmaxf(pcx - 0.5f * pw, 0.f), 1.f),
            fminf(fmaxf(pcy - 0.5f * ph, 0.f), 1.f),
            fminf(fmaxf(pcx + 0.5f * pw, 0.f), 1.f),
            fminf(fmaxf(pcy + 0.5f * ph, 0.f), 1.f));
    }
    // A_TOT % 32 == 0 -> warps never straddle images: (b,c) uniform per warp
#pragma unroll
    for (int c = 0; c < NFG; c++) {
        unsigned bin = 0; bool act = in;
        if (in) bin = __float_as_uint(fg[c]) >> 19;     // 12-bit bin (positive floats)
        unsigned tag = act ? bin : (NBIN + (threadIdx.x & 31));
        unsigned grp = __match_any_sync(0xffffffffu, tag);
        if (act && ((threadIdx.x & 31) == (unsigned)(__ffs(grp) - 1)))
            atomicAdd(&g_hist[(b * NFG + c) * NBIN + bin], __popc(grp));
    }
}

// ---------------- K2: find per-(b,c) threshold bin ---------------------------
__global__ void k_thr() {
    int bc = blockIdx.x;
    int tid = threadIdx.x;                      // 256 threads, 16 bins each
    const unsigned* h = g_hist + bc * NBIN;
    unsigned loc[16]; int s = 0;
    int base = tid * 16;
#pragma unroll
    for (int i = 0; i < 16; i++) { loc[i] = h[base + i]; s += (int)loc[i]; }
    __shared__ int csum[256];
    __shared__ int suf[257];
    csum[tid] = s;
    __syncthreads();
    if (tid == 0) {
        int acc = 0; suf[256] = 0;
        for (int t = 255; t >= 0; t--) { acc += csum[t]; suf[t] = acc; }
    }
    __syncthreads();
    int above = suf[tid + 1];                   // count in higher chunks
    if (above < KTOP && above + s >= KTOP) {    // crossing is in my chunk
        int cum = above;
        for (int i = 15; i >= 0; i--) {
            cum += (int)loc[i];
            if (cum >= KTOP) { g_thrbin[bc] = base + i; break; }
        }
    }
}

// ---------------- K3: single-pass candidate compaction -----------------------
__global__ void k_sel(const float* __restrict__ logits) {
    int idx = blockIdx.x * blockDim.x + threadIdx.x;
    bool in = idx < BATCH * A_TOT;
    int b = 0, a = 0;
    float fg[NFG];
    if (in) {
        b = idx / A_TOT; a = idx - b * A_TOT;
        float4 l0 = ((const float4*)logits)[idx * 2 + 0];
        float4 l1 = ((const float4*)logits)[idx * 2 + 1];
        softmax8(l0, l1, fg);
    }
    int lane = threadIdx.x & 31;
#pragma unroll
    for (int c = 0; c < NFG; c++) {
        int bc = b * NFG + c;                    // warp-uniform
        unsigned key = in ? __float_as_uint(fg[c]) : 0u;
        bool act = in && ((int)(key >> 19) >= g_thrbin[bc]);
        unsigned m = __ballot_sync(0xffffffffu, act);
        if (m) {
            int leader = __ffs(m) - 1;
            int bse = 0;
            if (lane == leader) bse = atomicAdd(&g_ccnt[bc], __popc(m));
            bse = __shfl_sync(0xffffffffu, bse, leader);
            if (act) {
                int pos = bse + __popc(m & ((1u << lane) - 1u));
                if (pos < CANDMAX)
                    g_cand[(size_t)bc * CANDMAX + pos] =
                        ((unsigned long long)key << 32) | (unsigned)(A_TOT - a);
            }
        }
    }
}

// ---------------- K4: sort candidates, exact top-200, NMS, compact -----------
__global__ void k_nms() {
    int bc = blockIdx.x;
    int b = bc / NFG;
    int tid = threadIdx.x;                      // 256 threads

    __shared__ unsigned long long sc[CANDMAX];
    int n = g_ccnt[bc]; if (n > CANDMAX) n = CANDMAX;
    int npad = 256; while (npad < n) npad <<= 1;
    for (int i = tid; i < npad; i += 256)
        sc[i] = (i < n) ? g_cand[(size_t)bc * CANDMAX + i] : 0ULL;
    __syncthreads();
    // bitonic sort descending (composite: key desc, anchor asc)
    for (int k = 2; k <= npad; k <<= 1)
        for (int j = k >> 1; j > 0; j >>= 1) {
            for (int t = tid; t < npad; t += 256) {
                int l = t ^ j;
                if (l > t) {
                    bool desc = ((t & k) == 0);
                    unsigned long long va = sc[t], vb = sc[l];
                    if (desc ? (va < vb) : (va > vb)) { sc[t] = vb; sc[l] = va; }
                }
            }
            __syncthreads();
        }

    __shared__ float x0[KTOP], y0[KTOP], x1[KTOP], y1[KTOP], ar[KTOP], ss[KTOP];
    __shared__ int   an[KTOP];
    __shared__ unsigned mask[KTOP * 7];
    __shared__ unsigned remw[7];
    __shared__ int woff[8];
    if (tid < KTOP) {
        unsigned long long v = sc[tid];
        unsigned key = (unsigned)(v >> 32);
        int a = A_TOT - (int)(v & 0xffffffffu);
        float4 bx = g_boxes[(size_t)b * A_TOT + a];
        x0[tid] = bx.x; y0[tid] = bx.y; x1[tid] = bx.z; y1[tid] = bx.w;
        ar[tid] = (bx.z - bx.x) * (bx.w - bx.y);
        ss[tid] = __uint_as_float(key); an[tid] = a;
    }
    for (int i = tid; i < KTOP * 7; i += 256) mask[i] = 0;
    __syncthreads();

    for (int p = tid; p < KTOP * KTOP; p += 256) {
        int i = p / KTOP, j = p - i * KTOP;
        if (j > i) {
            float xl = fmaxf(x0[i], x0[j]);
            float yt = fmaxf(y0[i], y0[j]);
            float xr = fminf(x1[i], x1[j]);
            float yb = fminf(y1[i], y1[j]);
            float inter = fmaxf(xr - xl, 0.f) * fmaxf(yb - yt, 0.f);
            float iou = inter / (ar[i] + ar[j] - inter);   // NaN -> false (matches jax)
            if (iou > NMS_THR_F) atomicOr(&mask[i * 7 + (j >> 5)], 1u << (j & 31));
        }
    }
    __syncthreads();

    // greedy scan by warp 0 (lanes 0..6 own the 7 removed-words)
    if (tid < 32) {
        unsigned rem = 0;
        if (tid < 7)
            for (int j = 0; j < 32; j++) {
                int jj = tid * 32 + j;
                if (jj < KTOP && !(ss[jj] > LOW_SCORE_F)) rem |= 1u << j;
            }
        for (int i = 0; i < KTOP; i++) {
            unsigned rw = __shfl_sync(0xffffffffu, rem, i >> 5);
            if (!((rw >> (i & 31)) & 1u))
                if (tid < 7) rem |= mask[i * 7 + tid];
        }
        if (tid < 7) remw[tid] = rem;
    }
    __syncthreads();

    // order-preserving compaction of kept entries
    if (tid == 0) {
        int s = 0;
        for (int w = 0; w < 7; w++) {
            unsigned valid = (w < 6) ? 0xffffffffu : 0xffu;   // 200 = 6*32+8
            woff[w] = s;
            s += __popc(~remw[w] & valid);
        }
        g_kcnt[bc] = s;
    }
    __syncthreads();
    if (tid < KTOP) {
        int w = tid >> 5;
        bool keep = !((remw[w] >> (tid & 31)) & 1u);
        if (keep) {
            int pos = woff[w] + __popc(~remw[w] & ((1u << (tid & 31)) - 1u));
            g_ks[bc * KTOP + pos] = ss[tid];
            g_km[bc * KTOP + pos] = an[tid];
        }
    }
}

// ---------------- K5: per-image rank-merge + emit top-200 --------------------
__global__ void k_out(float* __restrict__ out) {
    int b = blockIdx.x;
    int tid = threadIdx.x;                      // 1024 threads
    __shared__ float skey[NFG * KTOP];
    __shared__ int   san[NFG * KTOP];
    __shared__ int   scnt[NFG];
    __shared__ int   total;
    if (tid < NFG) scnt[tid] = g_kcnt[b * NFG + tid];
    for (int i = tid; i < NFG * KTOP; i += 1024) {
        skey[i] = g_ks[b * NFG * KTOP + i];
        san[i]  = g_km[b * NFG * KTOP + i];
    }
    if (tid == 0) {
        int t = 0;
        for (int c = 0; c < NFG; c++) t += g_kcnt[b * NFG + c];
        total = t < KTOP ? t : KTOP;
    }
    __syncthreads();
    // zero only slots that receive no element (disjoint from written slots)
    for (int i = total + tid; i < KTOP; i += 1024) {
        ((float4*)out)[b * KTOP + i] = make_float4(0.f, 0.f, 0.f, 0.f);
        out[BATCH * KTOP * 4 + b * KTOP + i] = 0.f;
        out[BATCH * KTOP * 5 + b * KTOP + i] = 0.f;
    }
    // each kept element computes its global rank via binary searches
    for (int i = tid; i < NFG * KTOP; i += 1024) {
        int c = i / KTOP, p = i - c * KTOP;
        if (p < scnt[c]) {
            float k = skey[i];
            int rank = p;                        // earlier in my own (sorted) list
#pragma unroll
            for (int c2 = 0; c2 < NFG; c2++) {
                if (c2 == c) continue;
                int lo = 0, hi = scnt[c2];
                while (lo < hi) {
                    int mid = (lo + hi) >> 1;
                    float v = skey[c2 * KTOP + mid];
                    bool prec = (v > k) || (v == k && c2 < c);
                    if (prec) lo = mid + 1; else hi = mid;
                }
                rank += lo;
            }
            if (rank < KTOP) {
                float4 bx = g_boxes[(size_t)b * A_TOT + san[i]];
                ((float4*)out)[b * KTOP + rank] = bx;
                out[BATCH * KTOP * 4 + b * KTOP + rank] = k;
                out[BATCH * KTOP * 5 + b * KTOP + rank] = (float)(c + 1);
            }
        }
    }
}

// -----------------------------------------------------------------------------
extern "C" void kernel_launch(void* const* d_in, const int* in_sizes, int n_in,
                              void* d_out, int out_size) {
    const float* logits = nullptr;
    const float* deltas = nullptr;
    const float* dbox   = nullptr;
    for (int i = 0; i < n_in; i++) {
        if      (in_sizes[i] == BATCH * A_TOT * 8) logits = (const float*)d_in[i];
        else if (in_sizes[i] == BATCH * A_TOT * 4) deltas = (const float*)d_in[i];
        else if (in_sizes[i] == A_TOT * 4)         dbox   = (const float*)d_in[i];
    }
    float* out = (float*)d_out;

    int nthreads = BATCH * A_TOT;
    k_zero<<<(NBC * NBIN + 255) / 256, 256>>>();
    k_prep<<<(nthreads + 255) / 256, 256>>>(logits, deltas, dbox);
    k_thr<<<NBC, 256>>>();
    k_sel<<<(nthreads + 255) / 256, 256>>>(logits);
    k_nms<<<NBC, 256>>>();
    k_out<<<BATCH, 1024>>>(out);
}

// round 4
// speedup vs baseline: 4.1643x; 1.5559x over previous
#include <cuda_runtime.h>
#include <cstdint>

#define A_TOT 49056
#define AHALF (A_TOT/2)          // 24528 key-pair words per (b,c) plane
#define QTOT  (AHALF/4)          // 6132 uint4 per plane
#define BATCH 32
#define NFG 7
#define KTOP 200
#define NBC (BATCH*NFG)          // 224
#define NBIN 2048
#define HSHIFT 21                // bin = key32 >> 21  (exp + 2 mantissa bits)
#define CANDMAX 4096
#define NMS_THR_F 0.45f
#define LOW_SCORE_F 0.01f

// ---------------- scratch (device globals) -----------------------------------
__device__ unsigned g_k16[(size_t)NBC * AHALF];   // packed (key16 lo | key16 hi)
__device__ unsigned g_hist[NBC * NBIN];
__device__ int g_thrbin[NBC];
__device__ unsigned g_cand[NBC * CANDMAX];        // anchor indices
__device__ int g_ccnt[NBC];
__device__ float g_ks[NBC * KTOP];                // kept scores (sorted desc)
__device__ int   g_km[NBC * KTOP];                // kept anchors
__device__ int   g_kcnt[NBC];

// identical softmax everywhere (bit-exact consistency across passes)
__device__ __forceinline__ void softmax8(const float4 l0, const float4 l1, float* fg7) {
    float x[8] = {l0.x, l0.y, l0.z, l0.w, l1.x, l1.y, l1.z, l1.w};
    float mx = x[0];
#pragma unroll
    for (int i = 1; i < 8; i++) mx = fmaxf(mx, x[i]);
    float e[8]; float sum = 0.f;
#pragma unroll
    for (int i = 0; i < 8; i++) { e[i] = expf(x[i] - mx); sum += e[i]; }
    float inv = 1.0f / sum;
#pragma unroll
    for (int c = 0; c < NFG; c++) fg7[c] = e[c + 1] * inv;
}

__device__ __forceinline__ float4 decode_box(float4 d, float4 db) {
    float w  = db.z - db.x,  h  = db.w - db.y;
    float cx = db.x + 0.5f * w, cy = db.y + 0.5f * h;
    float pcx = d.x / 10.0f * w + cx;
    float pcy = d.y / 10.0f * h + cy;
    float pw  = expf(d.z / 5.0f) * w;
    float ph  = expf(d.w / 5.0f) * h;
    return make_float4(
        fminf(fmaxf(pcx - 0.5f * pw, 0.f), 1.f),
        fminf(fmaxf(pcy - 0.5f * ph, 0.f), 1.f),
        fminf(fmaxf(pcx + 0.5f * pw, 0.f), 1.f),
        fminf(fmaxf(pcy + 0.5f * ph, 0.f), 1.f));
}

// ---------------- K0: zero scratch -------------------------------------------
__global__ void k_zero() {
    int i = blockIdx.x * 256 + threadIdx.x;
    if (i < NBC * NBIN) g_hist[i] = 0u;
    if (i < NBC) g_ccnt[i] = 0;
}

// ---------------- K1: softmax -> key16 planes + smem histogram ---------------
__global__ void k_prep(const float* __restrict__ logits) {
    int b = blockIdx.x >> 4;                   // 16 chunks per image
    int chunk = blockIdx.x & 15;
    int tid = threadIdx.x;
    __shared__ unsigned hist[NFG * (NBIN / 2)]; // u16-packed halves, 28 KB
    for (int i = tid; i < NFG * (NBIN / 2); i += 256) hist[i] = 0;
    __syncthreads();

    int wbase = chunk * 1536 + tid;
#pragma unroll
    for (int k = 0; k < 6; k++) {
        int w = wbase + k * 256;
        if (w < AHALF) {
            size_t aidx = (size_t)b * A_TOT + 2 * w;
            const float4* lp = (const float4*)logits + aidx * 2;
            float4 p0 = lp[0], p1 = lp[1], p2 = lp[2], p3 = lp[3];
            float f0[NFG], f1[NFG];
            softmax8(p0, p1, f0);
            softmax8(p2, p3, f1);
#pragma unroll
            for (int c = 0; c < NFG; c++) {
                unsigned k0 = __float_as_uint(f0[c]);
                unsigned k1 = __float_as_uint(f1[c]);
                g_k16[(size_t)(b * NFG + c) * AHALF + w] = (k0 >> 16) | ((k1 >> 16) << 16);
                unsigned b0 = k0 >> HSHIFT, b1 = k1 >> HSHIFT;
                atomicAdd(&hist[c * (NBIN / 2) + (b0 >> 1)], 1u << ((b0 & 1) * 16));
                atomicAdd(&hist[c * (NBIN / 2) + (b1 >> 1)], 1u << ((b1 & 1) * 16));
            }
        }
    }
    __syncthreads();
    for (int i = tid; i < NFG * (NBIN / 2); i += 256) {
        unsigned v = hist[i];
        if (!v) continue;
        int c = i / (NBIN / 2), bp = i % (NBIN / 2);
        unsigned lo = v & 0xffffu, hi = v >> 16;
        unsigned* gh = &g_hist[(b * NFG + c) * NBIN + bp * 2];
        if (lo) atomicAdd(gh, lo);
        if (hi) atomicAdd(gh + 1, hi);
    }
}

// ---------------- K2: per-(b,c) threshold bin --------------------------------
__global__ void k_thr() {
    int bc = blockIdx.x;
    int tid = threadIdx.x;                      // 256 threads, 8 bins each
    const unsigned* h = g_hist + bc * NBIN;
    unsigned loc[8]; int s = 0;
    int base = tid * 8;
#pragma unroll
    for (int i = 0; i < 8; i++) { loc[i] = h[base + i]; s += (int)loc[i]; }
    __shared__ int csum[256];
    __shared__ int suf[257];
    csum[tid] = s;
    __syncthreads();
    if (tid == 0) {
        int acc = 0; suf[256] = 0;
        for (int t = 255; t >= 0; t--) { acc += csum[t]; suf[t] = acc; }
    }
    __syncthreads();
    int above = suf[tid + 1];
    if (above < KTOP && above + s >= KTOP) {
        int cum = above;
        for (int i = 7; i >= 0; i--) {
            cum += (int)loc[i];
            if (cum >= KTOP) { g_thrbin[bc] = base + i; break; }
        }
    }
}

// ---------------- K3: candidate compaction from key16 planes -----------------
__global__ void k_sel() {
    int gt = blockIdx.x * 256 + threadIdx.x;    // 224*1536 threads total
    int plane = gt / 1536;
    int t = gt - plane * 1536;
    int thr = g_thrbin[plane];
    const uint4* p = (const uint4*)(g_k16 + (size_t)plane * AHALF);

    uint4 v[4];
    int cnt = 0;
#pragma unroll
    for (int j = 0; j < 4; j++) {
        int q = j * 1536 + t;
        if (q < QTOT) {
            v[j] = p[q];
            unsigned ws[4] = {v[j].x, v[j].y, v[j].z, v[j].w};
#pragma unroll
            for (int wi = 0; wi < 4; wi++) {
                cnt += ((int)((ws[wi] & 0xffffu) >> 5) >= thr);
                cnt += ((int)(ws[wi] >> 21) >= thr);
            }
        }
    }
    // warp inclusive scan of cnt
    unsigned lane = threadIdx.x & 31;
    int incl = cnt;
#pragma unroll
    for (int d = 1; d < 32; d <<= 1) {
        int n = __shfl_up_sync(0xffffffffu, incl, d);
        if (lane >= d) incl += n;
    }
    int total = __shfl_sync(0xffffffffu, incl, 31);
    int start = 0;
    if (lane == 31 && total) start = atomicAdd(&g_ccnt[plane], total);
    start = __shfl_sync(0xffffffffu, start, 31);
    int pos = start + incl - cnt;
    if (cnt) {
#pragma unroll
        for (int j = 0; j < 4; j++) {
            int q = j * 1536 + t;
            if (q < QTOT) {
                unsigned ws[4] = {v[j].x, v[j].y, v[j].z, v[j].w};
#pragma unroll
                for (int wi = 0; wi < 4; wi++) {
                    int w = q * 4 + wi;
                    if ((int)((ws[wi] & 0xffffu) >> 5) >= thr) {
                        if (pos < CANDMAX) g_cand[plane * CANDMAX + pos] = 2 * w;
                        pos++;
                    }
                    if ((int)(ws[wi] >> 21) >= thr) {
                        if (pos < CANDMAX) g_cand[plane * CANDMAX + pos] = 2 * w + 1;
                        pos++;
                    }
                }
            }
        }
    }
}

// ---------------- K4: exact sort + top-200 + NMS + compact -------------------
__global__ void k_nms(const float* __restrict__ logits,
                      const float* __restrict__ deltas,
                      const float* __restrict__ dbox) {
    int bc = blockIdx.x;
    int b = bc / NFG, c = bc % NFG;
    int tid = threadIdx.x;                      // 256 threads

    __shared__ unsigned long long sc[CANDMAX];  // 32 KB
    int n = g_ccnt[bc]; if (n > CANDMAX) n = CANDMAX;
    int npad = 256; while (npad < n) npad <<= 1;
    for (int i = tid; i < npad; i += 256) {
        unsigned long long e = 0ULL;
        if (i < n) {
            int a = (int)g_cand[bc * CANDMAX + i];
            const float4* lp = (const float4*)logits + ((size_t)b * A_TOT + a) * 2;
            float fg[NFG];
            softmax8(lp[0], lp[1], fg);
            unsigned key = __float_as_uint(fg[c]);
            e = ((unsigned long long)key << 32) | (unsigned)(A_TOT - a);
        }
        sc[i] = e;
    }
    __syncthreads();
    for (int k = 2; k <= npad; k <<= 1)
        for (int j = k >> 1; j > 0; j >>= 1) {
            for (int t = tid; t < npad; t += 256) {
                int l = t ^ j;
                if (l > t) {
                    bool desc = ((t & k) == 0);
                    unsigned long long va = sc[t], vb = sc[l];
                    if (desc ? (va < vb) : (va > vb)) { sc[t] = vb; sc[l] = va; }
                }
            }
            __syncthreads();
        }

    __shared__ float x0[KTOP], y0[KTOP], x1[KTOP], y1[KTOP], ar[KTOP], ss[KTOP];
    __shared__ int   an[KTOP];
    __shared__ unsigned mask[KTOP * 7];
    __shared__ unsigned remw[7];
    __shared__ int woff[8];
    if (tid < KTOP) {
        unsigned long long v = sc[tid];
        unsigned key = (unsigned)(v >> 32);
        int a = A_TOT - (int)(v & 0xffffffffu);
        float4 d  = ((const float4*)deltas)[(size_t)b * A_TOT + a];
        float4 db = ((const float4*)dbox)[a];
        float4 bx = decode_box(d, db);
        x0[tid] = bx.x; y0[tid] = bx.y; x1[tid] = bx.z; y1[tid] = bx.w;
        ar[tid] = (bx.z - bx.x) * (bx.w - bx.y);
        ss[tid] = __uint_as_float(key); an[tid] = a;
    }
    for (int i = tid; i < KTOP * 7; i += 256) mask[i] = 0;
    __syncthreads();

    for (int p = tid; p < KTOP * KTOP; p += 256) {
        int i = p / KTOP, j = p - i * KTOP;
        if (j > i) {
            float xl = fmaxf(x0[i], x0[j]);
            float yt = fmaxf(y0[i], y0[j]);
            float xr = fminf(x1[i], x1[j]);
            float yb = fminf(y1[i], y1[j]);
            float inter = fmaxf(xr - xl, 0.f) * fmaxf(yb - yt, 0.f);
            float iou = inter / (ar[i] + ar[j] - inter);   // NaN -> false (matches jax)
            if (iou > NMS_THR_F) atomicOr(&mask[i * 7 + (j >> 5)], 1u << (j & 31));
        }
    }
    __syncthreads();

    if (tid < 32) {
        unsigned rem = 0;
        if (tid < 7)
            for (int j = 0; j < 32; j++) {
                int jj = tid * 32 + j;
                if (jj < KTOP && !(ss[jj] > LOW_SCORE_F)) rem |= 1u << j;
            }
        for (int i = 0; i < KTOP; i++) {
            unsigned rw = __shfl_sync(0xffffffffu, rem, i >> 5);
            if (!((rw >> (i & 31)) & 1u))
                if (tid < 7) rem |= mask[i * 7 + tid];
        }
        if (tid < 7) remw[tid] = rem;
    }
    __syncthreads();

    if (tid == 0) {
        int s = 0;
        for (int w = 0; w < 7; w++) {
            unsigned valid = (w < 6) ? 0xffffffffu : 0xffu;   // 200 = 6*32+8
            woff[w] = s;
            s += __popc(~remw[w] & valid);
        }
        g_kcnt[bc] = s;
    }
    __syncthreads();
    if (tid < KTOP) {
        int w = tid >> 5;
        bool keep = !((remw[w] >> (tid & 31)) & 1u);
        if (keep) {
            int pos = woff[w] + __popc(~remw[w] & ((1u << (tid & 31)) - 1u));
            g_ks[bc * KTOP + pos] = ss[tid];
            g_km[bc * KTOP + pos] = an[tid];
        }
    }
}

// ---------------- K5: per-image rank-merge + decode + emit -------------------
__global__ void k_out(const float* __restrict__ deltas,
                      const float* __restrict__ dbox,
                      float* __restrict__ out) {
    int b = blockIdx.x;
    int tid = threadIdx.x;                      // 1024 threads
    __shared__ float skey[NFG * KTOP];
    __shared__ int   san[NFG * KTOP];
    __shared__ int   scnt[NFG];
    __shared__ int   total;
    if (tid < NFG) scnt[tid] = g_kcnt[b * NFG + tid];
    for (int i = tid; i < NFG * KTOP; i += 1024) {
        skey[i] = g_ks[b * NFG * KTOP + i];
        san[i]  = g_km[b * NFG * KTOP + i];
    }
    if (tid == 0) {
        int t = 0;
        for (int c = 0; c < NFG; c++) t += g_kcnt[b * NFG + c];
        total = t < KTOP ? t : KTOP;
    }
    __syncthreads();
    for (int i = total + tid; i < KTOP; i += 1024) {
        ((float4*)out)[b * KTOP + i] = make_float4(0.f, 0.f, 0.f, 0.f);
        out[BATCH * KTOP * 4 + b * KTOP + i] = 0.f;
        out[BATCH * KTOP * 5 + b * KTOP + i] = 0.f;
    }
    for (int i = tid; i < NFG * KTOP; i += 1024) {
        int c = i / KTOP, p = i - c * KTOP;
        if (p < scnt[c]) {
            float k = skey[i];
            int rank = p;
#pragma unroll
            for (int c2 = 0; c2 < NFG; c2++) {
                if (c2 == c) continue;
                int lo = 0, hi = scnt[c2];
                while (lo < hi) {
                    int mid = (lo + hi) >> 1;
                    float v = skey[c2 * KTOP + mid];
                    bool prec = (v > k) || (v == k && c2 < c);
                    if (prec) lo = mid + 1; else hi = mid;
                }
                rank += lo;
            }
            if (rank < KTOP) {
                int a = san[i];
                float4 d  = ((const float4*)deltas)[(size_t)b * A_TOT + a];
                float4 db = ((const float4*)dbox)[a];
                float4 bx = decode_box(d, db);
                ((float4*)out)[b * KTOP + rank] = bx;
                out[BATCH * KTOP * 4 + b * KTOP + rank] = k;
                out[BATCH * KTOP * 5 + b * KTOP + rank] = (float)(c + 1);
            }
        }
    }
}

// -----------------------------------------------------------------------------
extern "C" void kernel_launch(void* const* d_in, const int* in_sizes, int n_in,
                              void* d_out, int out_size) {
    const float* logits = nullptr;
    const float* deltas = nullptr;
    const float* dbox   = nullptr;
    for (int i = 0; i < n_in; i++) {
        if      (in_sizes[i] == BATCH * A_TOT * 8) logits = (const float*)d_in[i];
        else if (in_sizes[i] == BATCH * A_TOT * 4) deltas = (const float*)d_in[i];
        else if (in_sizes[i] == A_TOT * 4)         dbox   = (const float*)d_in[i];
    }
    float* out = (float*)d_out;

    k_zero<<<(NBC * NBIN + 255) / 256, 256>>>();
    k_prep<<<BATCH * 16, 256>>>(logits);
    k_thr<<<NBC, 256>>>();
    k_sel<<<(NBC * 1536) / 256, 256>>>();
    k_nms<<<NBC, 256>>>(logits, deltas, dbox);
    k_out<<<BATCH, 1024>>>(deltas, dbox, out);
}